// round 3
// baseline (speedup 1.0000x reference)
#include <cuda_runtime.h>

// Problem constants
#define NN      262144
#define HID     512
#define GATES   64
#define NG      1024

// Scratch (static __device__ globals — no allocation)
__device__ float g_gate[(size_t)NN * GATES];   // 64 MB gate logits
__device__ float g_w[NN];                      // per-node pooled weight

// ---------------------------------------------------------------------------
// Packed f32x2 helpers (Blackwell sm_100+)
// ---------------------------------------------------------------------------
__device__ __forceinline__ unsigned long long fma2(unsigned long long a,
                                                   unsigned long long b,
                                                   unsigned long long c) {
    unsigned long long d;
    asm("fma.rn.f32x2 %0, %1, %2, %3;" : "=l"(d) : "l"(a), "l"(b), "l"(c));
    return d;
}
__device__ __forceinline__ unsigned long long dupf(float v) {
    unsigned long long d;
    asm("mov.b64 %0, {%1, %1};" : "=l"(d) : "f"(v));
    return d;
}
__device__ __forceinline__ void unpack2(unsigned long long v, float& a, float& b) {
    asm("mov.b64 {%0, %1}, %2;" : "=f"(a), "=f"(b) : "l"(v));
}

// ---------------------------------------------------------------------------
// Kernel 1: gate = x @ W   ([N,512] @ [512,64] -> [N,64], fp32)
// Block: 128 threads, tile 128 rows x 64 cols, thread tile 8x8 (row-paired f32x2)
// ---------------------------------------------------------------------------
#define KT 16
__global__ __launch_bounds__(128) void gemm_gate(const float* __restrict__ x,
                                                 const float* __restrict__ W) {
    __shared__ __align__(16) float xs[KT][128];   // transposed x tile: [k][row]
    __shared__ __align__(16) float ws[KT * 64];   // W tile, flat (k-major)

    const int tid = threadIdx.x;
    const int rowBase = blockIdx.x * 128;
    const int r0 = (tid >> 3) << 3;   // 0..120 step 8
    const int c0 = (tid & 7) << 3;    // 0..56  step 8

    unsigned long long acc[4][8];
#pragma unroll
    for (int a = 0; a < 4; a++)
#pragma unroll
        for (int b = 0; b < 8; b++) acc[a][b] = 0ull;

    const float* xrow = x + (size_t)(rowBase + tid) * HID;  // this thread stages one row

    float4 px[4], pw[2];
    // prefetch tile 0
    {
        const float4* p = (const float4*)(xrow);
        px[0] = p[0]; px[1] = p[1]; px[2] = p[2]; px[3] = p[3];
        const float4* q = (const float4*)(W);
        pw[0] = q[tid]; pw[1] = q[tid + 128];
    }

    for (int t = 0; t < HID / KT; t++) {
        // stage regs -> smem (transpose x; conflict-free: lane == row)
#pragma unroll
        for (int j = 0; j < 4; j++) {
            xs[j * 4 + 0][tid] = px[j].x;
            xs[j * 4 + 1][tid] = px[j].y;
            xs[j * 4 + 2][tid] = px[j].z;
            xs[j * 4 + 3][tid] = px[j].w;
        }
        ((float4*)ws)[tid]       = pw[0];
        ((float4*)ws)[tid + 128] = pw[1];
        __syncthreads();

        // prefetch next tile (overlap LDG with compute)
        if (t + 1 < HID / KT) {
            const float4* p = (const float4*)(xrow + (t + 1) * KT);
            px[0] = p[0]; px[1] = p[1]; px[2] = p[2]; px[3] = p[3];
            const float4* q = (const float4*)(W + (size_t)(t + 1) * KT * 64);
            pw[0] = q[tid]; pw[1] = q[tid + 128];
        }

#pragma unroll
        for (int k = 0; k < KT; k++) {
            // row pairs come packed for free from shared memory
            ulonglong2 a01 = *(const ulonglong2*)&xs[k][r0];
            ulonglong2 a23 = *(const ulonglong2*)&xs[k][r0 + 4];
            unsigned long long ap[4] = {a01.x, a01.y, a23.x, a23.y};
            float4 b0 = *(const float4*)&ws[k * 64 + c0];
            float4 b1 = *(const float4*)&ws[k * 64 + c0 + 4];
            unsigned long long bd[8];
            bd[0] = dupf(b0.x); bd[1] = dupf(b0.y); bd[2] = dupf(b0.z); bd[3] = dupf(b0.w);
            bd[4] = dupf(b1.x); bd[5] = dupf(b1.y); bd[6] = dupf(b1.z); bd[7] = dupf(b1.w);
#pragma unroll
            for (int rp = 0; rp < 4; rp++)
#pragma unroll
                for (int c = 0; c < 8; c++)
                    acc[rp][c] = fma2(ap[rp], bd[c], acc[rp][c]);
        }
        __syncthreads();
    }

    // epilogue: unpack row pairs, store gate
#pragma unroll
    for (int rp = 0; rp < 4; rp++) {
        float lo[8], hi[8];
#pragma unroll
        for (int c = 0; c < 8; c++) unpack2(acc[rp][c], lo[c], hi[c]);
        size_t rowA = (size_t)(rowBase + r0 + rp * 2);
        float4* pA = (float4*)&g_gate[rowA * 64 + c0];
        float4* pB = (float4*)&g_gate[(rowA + 1) * 64 + c0];
        pA[0] = make_float4(lo[0], lo[1], lo[2], lo[3]);
        pA[1] = make_float4(lo[4], lo[5], lo[6], lo[7]);
        pB[0] = make_float4(hi[0], hi[1], hi[2], hi[3]);
        pB[1] = make_float4(hi[4], hi[5], hi[6], hi[7]);
    }
}

// ---------------------------------------------------------------------------
// batch index loader: handles int64 (x64 enabled) or int32 (x64 disabled)
// ---------------------------------------------------------------------------
__device__ __forceinline__ long long load_batch(const void* b, bool is64, int i) {
    return is64 ? ((const long long*)b)[i] : (long long)((const int*)b)[i];
}
__device__ int lower_bound_batch(const void* b, bool is64, long long val) {
    int lo = 0, hi = NN;
    while (lo < hi) {
        int mid = (lo + hi) >> 1;
        if (load_batch(b, is64, mid) < val) lo = mid + 1; else hi = mid;
    }
    return lo;
}

// ---------------------------------------------------------------------------
// Kernel 2: per-graph segment softmax + mean-gate weight + weighted pooling
// One block per graph (batch is sorted). 256 threads. Deterministic (no atomics).
// ---------------------------------------------------------------------------
__global__ __launch_bounds__(256) void softmax_pool(const float* __restrict__ x,
                                                    const void* __restrict__ batch,
                                                    float* __restrict__ out) {
    __shared__ float red[256];
    __shared__ float sm_m[64];
    __shared__ float sm_r[64];
    __shared__ int seg[2];

    const int tid = threadIdx.x;
    const int g = blockIdx.x;

    if (tid == 0) {
        // dtype probe: safely inside the buffer for both int32 and int64 layouts.
        // int64 data -> value in [0, NG); int32 data -> combines two sorted ints,
        // high word ~1023 -> value >= 2^32.
        long long probe = ((const long long*)batch)[NN / 2 - 1];
        bool is64 = (probe >= 0 && probe < (long long)NG);
        seg[0] = lower_bound_batch(batch, is64, (long long)g);
        seg[1] = lower_bound_batch(batch, is64, (long long)g + 1);
    }
    __syncthreads();
    const int st = seg[0], en = seg[1];

    // ---- Pass A: per-gate-column segment max ----
    const int k = tid & 63, grp = tid >> 6;   // 64 cols x 4 row-groups
    float m = -3.402823466e38f;
    for (int i = st + grp; i < en; i += 4)
        m = fmaxf(m, g_gate[(size_t)i * 64 + k]);
    red[tid] = m;
    __syncthreads();
    if (tid < 64)
        sm_m[tid] = fmaxf(fmaxf(red[tid], red[tid + 64]),
                          fmaxf(red[tid + 128], red[tid + 192]));
    __syncthreads();

    // ---- Pass B: per-column sum of exp ----
    const float mk = sm_m[k];
    float s = 0.f;
    for (int i = st + grp; i < en; i += 4)
        s += __expf(g_gate[(size_t)i * 64 + k] - mk);
    red[tid] = s;
    __syncthreads();
    if (tid < 64) {
        float ss = red[tid] + red[tid + 64] + red[tid + 128] + red[tid + 192];
        sm_r[tid] = 1.0f / (ss + 1e-16f) * (1.0f / 64.0f);   // fold mean into recip
    }
    __syncthreads();

    // ---- Pass C: per-node weight = mean_k softmax(gate)[i,k] ----
    const int warp = tid >> 5, lane = tid & 31;
    const float mA = sm_m[lane], mB = sm_m[lane + 32];
    const float rA = sm_r[lane], rB = sm_r[lane + 32];
    for (int i = st + warp; i < en; i += 8) {
        float w = __expf(g_gate[(size_t)i * 64 + lane] - mA) * rA
                + __expf(g_gate[(size_t)i * 64 + 32 + lane] - mB) * rB;
#pragma unroll
        for (int off = 16; off; off >>= 1) w += __shfl_xor_sync(0xffffffffu, w, off);
        if (lane == 0) g_w[i] = w;
    }
    __syncthreads();   // g_w visible block-wide

    // ---- Pass D: out[g] = sum_i w_i * x_i  (each thread owns 2 hidden cols) ----
    float a0 = 0.f, a1 = 0.f;
    int i = st;
    for (; i + 4 <= en; i += 4) {
        float w0 = g_w[i], w1 = g_w[i + 1], w2 = g_w[i + 2], w3 = g_w[i + 3];
        const float* p = x + (size_t)i * HID + tid;
        a0 += w0 * p[0];    a1 += w0 * p[256];
        a0 += w1 * p[512];  a1 += w1 * p[768];
        a0 += w2 * p[1024]; a1 += w2 * p[1280];
        a0 += w3 * p[1536]; a1 += w3 * p[1792];
    }
    for (; i < en; i++) {
        float w = g_w[i];
        a0 += w * x[(size_t)i * HID + tid];
        a1 += w * x[(size_t)i * HID + tid + 256];
    }
    out[(size_t)g * HID + tid]       = a0;   // writes all of d_out (incl. empty graphs)
    out[(size_t)g * HID + tid + 256] = a1;
}

// ---------------------------------------------------------------------------
extern "C" void kernel_launch(void* const* d_in, const int* in_sizes, int n_in,
                              void* d_out, int out_size) {
    const float* x = nullptr;
    const float* W = nullptr;
    const void* batch = nullptr;
    for (int i = 0; i < n_in; i++) {
        if (in_sizes[i] == NN * HID)          x = (const float*)d_in[i];
        else if (in_sizes[i] == HID * GATES)  W = (const float*)d_in[i];
        else if (in_sizes[i] == NN)           batch = d_in[i];
    }
    float* out = (float*)d_out;

    gemm_gate<<<NN / 128, 128>>>(x, W);
    softmax_pool<<<NG, 256>>>(x, batch, out);
}

// round 6
// speedup vs baseline: 1.8418x; 1.8418x over previous
#include <cuda_runtime.h>
#include <cuda_bf16.h>
#include <cstdint>

// Problem constants
#define NN      262144
#define HID     512
#define GATES   64
#define NG      1024

// Scratch (static __device__ globals — no allocation)
__device__ float g_gate[(size_t)NN * GATES];            // 64 MB gate logits
__device__ float g_w[NN];                               // per-node pooled weight
__device__ __nv_bfloat16 g_bh[GATES * HID];             // W^T hi, [n][k] row-major
__device__ __nv_bfloat16 g_bl[GATES * HID];             // W^T lo

// ---------------------------------------------------------------------------
// Helpers
// ---------------------------------------------------------------------------
__device__ __forceinline__ uint32_t smem_u32(const void* p) {
    uint32_t a;
    asm("{ .reg .u64 t; cvta.to.shared.u64 t, %1; cvt.u32.u64 %0, t; }" : "=r"(a) : "l"(p));
    return a;
}
// SW128 swizzle (XOR bits[6:4] with bits[9:7]) — used consistently on both
// the staging stores and the ldmatrix reads, so layout is self-consistent
// and conflict-free (8 rows of an ldmatrix phase land in 8 distinct 16B banks).
#define SW128(o) ((o) ^ ((((uint32_t)(o)) >> 3) & 0x70u))

__device__ __forceinline__ void ldm_x4(uint32_t r[4], uint32_t addr) {
    asm volatile("ldmatrix.sync.aligned.m8n8.x4.shared.b16 {%0,%1,%2,%3}, [%4];"
                 : "=r"(r[0]), "=r"(r[1]), "=r"(r[2]), "=r"(r[3]) : "r"(addr));
}
__device__ __forceinline__ void mma_bf16(float d[4], const uint32_t a[4],
                                         const uint32_t b[2]) {
    asm volatile(
        "mma.sync.aligned.m16n8k16.row.col.f32.bf16.bf16.f32 "
        "{%0,%1,%2,%3}, {%4,%5,%6,%7}, {%8,%9}, {%0,%1,%2,%3};"
        : "+f"(d[0]), "+f"(d[1]), "+f"(d[2]), "+f"(d[3])
        : "r"(a[0]), "r"(a[1]), "r"(a[2]), "r"(a[3]), "r"(b[0]), "r"(b[1]));
}

// SMEM layout: A tiles 128 rows x 128B (64 bf16), B tiles 64 rows x 128B
#define SM_AHI    0
#define SM_ALO    16384
#define SM_BHI    32768
#define SM_BLO    40960
#define SM_TOTAL  49152

// ---------------------------------------------------------------------------
// Kernel 0: split/transpose W [512k][64n] fp32 -> g_bh/g_bl [64n][512k] bf16
// ---------------------------------------------------------------------------
__global__ void prep_w(const float* __restrict__ W) {
    for (int idx = blockIdx.x * 256 + threadIdx.x; idx < HID * GATES; idx += gridDim.x * 256) {
        int k = idx >> 6, n = idx & 63;
        float v = W[idx];
        __nv_bfloat16 hi = __float2bfloat16(v);
        __nv_bfloat16 lo = __float2bfloat16(v - __bfloat162float(hi));
        g_bh[n * HID + k] = hi;
        g_bl[n * HID + k] = lo;
    }
}

// ---------------------------------------------------------------------------
// Kernel 1: gate = x @ W via mma.sync bf16 hi/lo split (3-pass, fp32-accurate)
// CTA: 128 rows x 64 gates, K=512 in 8 chunks of 64. 256 threads = 8 warps.
// Warp grid 4(m) x 2(n): each warp computes 32x32 (2 m-tiles x 4 n-tiles).
// ---------------------------------------------------------------------------
__global__ __launch_bounds__(256) void gemm_tc(const float* __restrict__ x) {
    extern __shared__ __align__(1024) char smem[];
    const uint32_t sb = smem_u32(smem);
    const int tid = threadIdx.x, wid = tid >> 5, lane = tid & 31;
    const int rowBase = blockIdx.x * 128;
    const int wm = (wid >> 1) * 32, wn = (wid & 1) * 32;
    const int sub = lane >> 3, rr = lane & 7;   // ldmatrix address helpers

    float acc[2][4][4];
#pragma unroll
    for (int mt = 0; mt < 2; mt++)
#pragma unroll
        for (int nt = 0; nt < 4; nt++)
#pragma unroll
            for (int q = 0; q < 4; q++) acc[mt][nt][q] = 0.f;

    for (int c = 0; c < 8; c++) {
        // ---- stage A chunk: x[rowBase..+128, c*64..+64) -> bf16 hi/lo, SW128 ----
#pragma unroll
        for (int it = 0; it < 8; it++) {
            int idx = tid + it * 256;          // 0..2047 (128 rows x 16 float4)
            int row = idx >> 4, q = idx & 15;
            float4 v = *(const float4*)(x + (size_t)(rowBase + row) * HID + c * 64 + q * 4);
            __nv_bfloat16 h0 = __float2bfloat16(v.x), h1 = __float2bfloat16(v.y);
            __nv_bfloat16 h2 = __float2bfloat16(v.z), h3 = __float2bfloat16(v.w);
            __nv_bfloat16 l0 = __float2bfloat16(v.x - __bfloat162float(h0));
            __nv_bfloat16 l1 = __float2bfloat16(v.y - __bfloat162float(h1));
            __nv_bfloat16 l2 = __float2bfloat16(v.z - __bfloat162float(h2));
            __nv_bfloat16 l3 = __float2bfloat16(v.w - __bfloat162float(h3));
            uint32_t hA = ((uint32_t)__bfloat16_as_ushort(h1) << 16) | __bfloat16_as_ushort(h0);
            uint32_t hB = ((uint32_t)__bfloat16_as_ushort(h3) << 16) | __bfloat16_as_ushort(h2);
            uint32_t lA = ((uint32_t)__bfloat16_as_ushort(l1) << 16) | __bfloat16_as_ushort(l0);
            uint32_t lB = ((uint32_t)__bfloat16_as_ushort(l3) << 16) | __bfloat16_as_ushort(l2);
            uint32_t off = SW128((uint32_t)(row * 128 + q * 8));
            *(uint2*)(smem + SM_AHI + off) = make_uint2(hA, hB);
            *(uint2*)(smem + SM_ALO + off) = make_uint2(lA, lB);
        }
        // ---- stage B chunk: g_bh/g_bl [64n][512k] slice cols c*64..+64 ----
#pragma unroll
        for (int it = 0; it < 2; it++) {
            int idx = tid + it * 256;          // 0..511 (64 rows x 8 uint4)
            int n = idx >> 3, j = idx & 7;
            size_t src = ((size_t)n * HID + c * 64) * 2 + j * 16;
            uint4 vh = *(const uint4*)((const char*)g_bh + src);
            uint4 vl = *(const uint4*)((const char*)g_bl + src);
            uint32_t off = SW128((uint32_t)(n * 128 + j * 16));
            *(uint4*)(smem + SM_BHI + off) = vh;
            *(uint4*)(smem + SM_BLO + off) = vl;
        }
        __syncthreads();

        // ---- compute: 4 k-steps of 16; 3 passes (AhBh + AhBl + AlBh) ----
#pragma unroll
        for (int ks = 0; ks < 4; ks++) {
            const int kOff = ks * 16;
            uint32_t ah[2][4], al[2][4], bh[2][4], bl[2][4];
#pragma unroll
            for (int mt = 0; mt < 2; mt++) {
                // x4: {a0(mlo,klo) t0-7, a1(mhi,klo) t8-15, a2(mlo,khi), a3(mhi,khi)}
                uint32_t off = SW128((uint32_t)(
                    (wm + mt * 16 + (sub & 1) * 8 + rr) * 128 +
                    (kOff + (sub >> 1) * 8) * 2));
                ldm_x4(ah[mt], sb + SM_AHI + off);
                ldm_x4(al[mt], sb + SM_ALO + off);
            }
#pragma unroll
            for (int np = 0; np < 2; np++) {
                // x4: {b0 ntile0, b1 ntile0, b0 ntile1, b1 ntile1}
                uint32_t off = SW128((uint32_t)(
                    (wn + np * 16 + (sub >> 1) * 8 + rr) * 128 +
                    (kOff + (sub & 1) * 8) * 2));
                ldm_x4(bh[np], sb + SM_BHI + off);
                ldm_x4(bl[np], sb + SM_BLO + off);
            }
#pragma unroll
            for (int mt = 0; mt < 2; mt++)
#pragma unroll
                for (int nt = 0; nt < 4; nt++) {
                    const uint32_t* pbh = &bh[nt >> 1][(nt & 1) * 2];
                    const uint32_t* pbl = &bl[nt >> 1][(nt & 1) * 2];
                    mma_bf16(acc[mt][nt], ah[mt], pbh);   // hi * hi
                    mma_bf16(acc[mt][nt], ah[mt], pbl);   // hi * lo
                    mma_bf16(acc[mt][nt], al[mt], pbh);   // lo * hi
                }
        }
        __syncthreads();
    }

    // ---- epilogue: write accumulators to g_gate ----
    // D frag m16n8: thread holds rows lane/4 and lane/4+8, cols 2*(lane&3),+1
#pragma unroll
    for (int mt = 0; mt < 2; mt++)
#pragma unroll
        for (int nt = 0; nt < 4; nt++) {
            int r = rowBase + wm + mt * 16 + (lane >> 2);
            int cc = wn + nt * 8 + (lane & 3) * 2;
            *(float2*)&g_gate[(size_t)r * 64 + cc] =
                make_float2(acc[mt][nt][0], acc[mt][nt][1]);
            *(float2*)&g_gate[(size_t)(r + 8) * 64 + cc] =
                make_float2(acc[mt][nt][2], acc[mt][nt][3]);
        }
}

// ---------------------------------------------------------------------------
// batch index loader: handles int64 (x64 enabled) or int32 (x64 disabled)
// ---------------------------------------------------------------------------
__device__ __forceinline__ long long load_batch(const void* b, bool is64, int i) {
    return is64 ? ((const long long*)b)[i] : (long long)((const int*)b)[i];
}
__device__ int lower_bound_batch(const void* b, bool is64, long long val) {
    int lo = 0, hi = NN;
    while (lo < hi) {
        int mid = (lo + hi) >> 1;
        if (load_batch(b, is64, mid) < val) lo = mid + 1; else hi = mid;
    }
    return lo;
}

// ---------------------------------------------------------------------------
// Kernel 2: per-graph segment softmax + mean-gate weight + weighted pooling
// (unchanged from passing version)
// ---------------------------------------------------------------------------
__global__ __launch_bounds__(256) void softmax_pool(const float* __restrict__ x,
                                                    const void* __restrict__ batch,
                                                    float* __restrict__ out) {
    __shared__ float red[256];
    __shared__ float sm_m[64];
    __shared__ float sm_r[64];
    __shared__ int seg[2];

    const int tid = threadIdx.x;
    const int g = blockIdx.x;

    if (tid == 0) {
        long long probe = ((const long long*)batch)[NN / 2 - 1];
        bool is64 = (probe >= 0 && probe < (long long)NG);
        seg[0] = lower_bound_batch(batch, is64, (long long)g);
        seg[1] = lower_bound_batch(batch, is64, (long long)g + 1);
    }
    __syncthreads();
    const int st = seg[0], en = seg[1];

    // Pass A: per-gate-column segment max
    const int k = tid & 63, grp = tid >> 6;
    float m = -3.402823466e38f;
    for (int i = st + grp; i < en; i += 4)
        m = fmaxf(m, g_gate[(size_t)i * 64 + k]);
    red[tid] = m;
    __syncthreads();
    if (tid < 64)
        sm_m[tid] = fmaxf(fmaxf(red[tid], red[tid + 64]),
                          fmaxf(red[tid + 128], red[tid + 192]));
    __syncthreads();

    // Pass B: per-column sum of exp
    const float mk = sm_m[k];
    float s = 0.f;
    for (int i = st + grp; i < en; i += 4)
        s += __expf(g_gate[(size_t)i * 64 + k] - mk);
    red[tid] = s;
    __syncthreads();
    if (tid < 64) {
        float ss = red[tid] + red[tid + 64] + red[tid + 128] + red[tid + 192];
        sm_r[tid] = 1.0f / (ss + 1e-16f) * (1.0f / 64.0f);
    }
    __syncthreads();

    // Pass C: per-node weight = mean_k softmax(gate)[i,k]
    const int warp = tid >> 5, lane = tid & 31;
    const float mA = sm_m[lane], mB = sm_m[lane + 32];
    const float rA = sm_r[lane], rB = sm_r[lane + 32];
    for (int i = st + warp; i < en; i += 8) {
        float w = __expf(g_gate[(size_t)i * 64 + lane] - mA) * rA
                + __expf(g_gate[(size_t)i * 64 + 32 + lane] - mB) * rB;
#pragma unroll
        for (int off = 16; off; off >>= 1) w += __shfl_xor_sync(0xffffffffu, w, off);
        if (lane == 0) g_w[i] = w;
    }
    __syncthreads();

    // Pass D: out[g] = sum_i w_i * x_i
    float a0 = 0.f, a1 = 0.f;
    int i = st;
    for (; i + 4 <= en; i += 4) {
        float w0 = g_w[i], w1 = g_w[i + 1], w2 = g_w[i + 2], w3 = g_w[i + 3];
        const float* p = x + (size_t)i * HID + tid;
        a0 += w0 * p[0];    a1 += w0 * p[256];
        a0 += w1 * p[512];  a1 += w1 * p[768];
        a0 += w2 * p[1024]; a1 += w2 * p[1280];
        a0 += w3 * p[1536]; a1 += w3 * p[1792];
    }
    for (; i < en; i++) {
        float w = g_w[i];
        a0 += w * x[(size_t)i * HID + tid];
        a1 += w * x[(size_t)i * HID + tid + 256];
    }
    out[(size_t)g * HID + tid]       = a0;
    out[(size_t)g * HID + tid + 256] = a1;
}

// ---------------------------------------------------------------------------
extern "C" void kernel_launch(void* const* d_in, const int* in_sizes, int n_in,
                              void* d_out, int out_size) {
    const float* x = nullptr;
    const float* W = nullptr;
    const void* batch = nullptr;
    for (int i = 0; i < n_in; i++) {
        if (in_sizes[i] == NN * HID)          x = (const float*)d_in[i];
        else if (in_sizes[i] == HID * GATES)  W = (const float*)d_in[i];
        else if (in_sizes[i] == NN)           batch = d_in[i];
    }
    float* out = (float*)d_out;

    cudaFuncSetAttribute(gemm_tc, cudaFuncAttributeMaxDynamicSharedMemorySize, SM_TOTAL);

    prep_w<<<32, 256>>>(W);
    gemm_tc<<<NN / 128, 256, SM_TOTAL>>>(x);
    softmax_pool<<<NG, 256>>>(x, batch, out);
}